// round 5
// baseline (speedup 1.0000x reference)
#include <cuda_runtime.h>
#include <math_constants.h>

#define BATCH 4
#define SEQ   2048
#define DIM   1024

// Scratch (static device arrays: allocation-guard-safe)
__device__ float d_Q[BATCH * SEQ * DIM];
__device__ float d_K[BATCH * SEQ * DIM];
__device__ float d_V[BATCH * SEQ * DIM];
__device__ float d_S[(size_t)BATCH * SEQ * SEQ];   // scores -> probabilities in place
__device__ float d_xr[BATCH * SEQ * DIM];          // tf32-rounded x
__device__ float d_Wr[3][DIM * DIM];               // tf32-rounded Wq/Wk/Wv

// ---------------------------------------------------------------------------
// TF32 tensor-core GEMM building blocks
// Block tile 128x128, BK=16, 256 threads = 8 warps (2x4), warp tile 64x32.
// All mma operands are PRE-ROUNDED to tf32 in gmem, so the inner loop feeds
// raw fp32 bits to mma (no cvt in the hot path).
// ---------------------------------------------------------------------------

#define SA_STRIDE 20     // 16 + 4 pad: fragment loads bank-conflict-free
#define SBNN_STRIDE 136  // 128 + 8 pad for [k][n] layout (PV)

__device__ __forceinline__ unsigned f2tf(float x) {
    unsigned u;
    asm("cvt.rna.tf32.f32 %0, %1;" : "=r"(u) : "f"(x));
    return u;
}
__device__ __forceinline__ float tf32r(float x) { return __uint_as_float(f2tf(x)); }

__device__ __forceinline__ void mma_tf32(float* d, const unsigned* a, const unsigned* b) {
    asm volatile(
        "mma.sync.aligned.m16n8k8.row.col.f32.tf32.tf32.f32 "
        "{%0,%1,%2,%3}, {%4,%5,%6,%7}, {%8,%9}, {%0,%1,%2,%3};\n"
        : "+f"(d[0]), "+f"(d[1]), "+f"(d[2]), "+f"(d[3])
        : "r"(a[0]), "r"(a[1]), "r"(a[2]), "r"(a[3]), "r"(b[0]), "r"(b[1]));
}

__device__ __forceinline__ void cp16(void* smem, const void* gmem) {
    unsigned s = (unsigned)__cvta_generic_to_shared(smem);
    asm volatile("cp.async.cg.shared.global [%0], [%1], 16;\n" :: "r"(s), "l"(gmem));
}
__device__ __forceinline__ void cp_commit() { asm volatile("cp.async.commit_group;\n"); }
__device__ __forceinline__ void cp_wait1() { asm volatile("cp.async.wait_group 1;\n"); }
__device__ __forceinline__ void cp_wait0() { asm volatile("cp.async.wait_group 0;\n"); }

// Load one 128x16 K-contiguous tile (A or NT-B) into smem [128][SA_STRIDE].
__device__ __forceinline__ void load_tile_kmajor(float* s, const float* g, int ld, int t) {
    const int row = t >> 2;            // 0..63
    const int c4  = (t & 3) << 2;      // 0,4,8,12
    cp16(&s[row * SA_STRIDE + c4],        g + (size_t)row * ld + c4);
    cp16(&s[(row + 64) * SA_STRIDE + c4], g + (size_t)(row + 64) * ld + c4);
}

// Load one 16x128 [k][n] tile (PV's V) into smem [16][SBNN_STRIDE].
__device__ __forceinline__ void load_tile_nmajor(float* s, const float* g, int ld, int t) {
    const int kr = t >> 5;             // 0..7
    const int c4 = (t & 31) << 2;      // 0..124
    cp16(&s[kr * SBNN_STRIDE + c4],       g + (size_t)kr * ld + c4);
    cp16(&s[(kr + 8) * SBNN_STRIDE + c4], g + (size_t)(kr + 8) * ld + c4);
}

// One BK=16 compute step, NT layout. aBase/bBase are per-thread hoisted bases:
//   aBase = sA + (m_off+g)*SA_STRIDE + c,  bBase = sB + (n_off+g)*SA_STRIDE + c
__device__ __forceinline__ void mma_step_NT(const float* aBase, const float* bBase,
                                            float acc[4][4][4]) {
#pragma unroll
    for (int kb = 0; kb < 16; kb += 8) {
        unsigned a[4][4], b[4][2];
#pragma unroll
        for (int im = 0; im < 4; ++im) {
            const int r = im * 16 * SA_STRIDE;
            a[im][0] = __float_as_uint(aBase[r + kb]);
            a[im][1] = __float_as_uint(aBase[r + 8 * SA_STRIDE + kb]);
            a[im][2] = __float_as_uint(aBase[r + kb + 4]);
            a[im][3] = __float_as_uint(aBase[r + 8 * SA_STRIDE + kb + 4]);
        }
#pragma unroll
        for (int jn = 0; jn < 4; ++jn) {
            const int nn = jn * 8 * SA_STRIDE;
            b[jn][0] = __float_as_uint(bBase[nn + kb]);
            b[jn][1] = __float_as_uint(bBase[nn + kb + 4]);
        }
#pragma unroll
        for (int im = 0; im < 4; ++im)
#pragma unroll
            for (int jn = 0; jn < 4; ++jn)
                mma_tf32(acc[im][jn], a[im], b[jn]);
    }
}

// One BK=16 compute step, NN layout.
//   aBase = sA + (m_off+g)*SA_STRIDE + c,  bBase = sB + c*SBNN_STRIDE + n_off + g
__device__ __forceinline__ void mma_step_NN(const float* aBase, const float* bBase,
                                            float acc[4][4][4]) {
#pragma unroll
    for (int kb = 0; kb < 16; kb += 8) {
        unsigned a[4][4], b[4][2];
#pragma unroll
        for (int im = 0; im < 4; ++im) {
            const int r = im * 16 * SA_STRIDE;
            a[im][0] = __float_as_uint(aBase[r + kb]);
            a[im][1] = __float_as_uint(aBase[r + 8 * SA_STRIDE + kb]);
            a[im][2] = __float_as_uint(aBase[r + kb + 4]);
            a[im][3] = __float_as_uint(aBase[r + 8 * SA_STRIDE + kb + 4]);
        }
#pragma unroll
        for (int jn = 0; jn < 4; ++jn) {
            const int nn = jn * 8;
            b[jn][0] = __float_as_uint(bBase[kb * SBNN_STRIDE + nn]);
            b[jn][1] = __float_as_uint(bBase[(kb + 4) * SBNN_STRIDE + nn]);
        }
#pragma unroll
        for (int im = 0; im < 4; ++im)
#pragma unroll
            for (int jn = 0; jn < 4; ++jn)
                mma_tf32(acc[im][jn], a[im], b[jn]);
    }
}

template <bool ROUND>
__device__ __forceinline__ void store_acc(float* C, int ldc, int m0, int n0,
                                          int m_off, int n_off, int g, int c,
                                          float acc[4][4][4]) {
#pragma unroll
    for (int im = 0; im < 4; ++im) {
#pragma unroll
        for (int jn = 0; jn < 4; ++jn) {
            const int row = m0 + m_off + im * 16 + g;
            const int col = n0 + n_off + jn * 8 + 2 * c;
            float v0 = acc[im][jn][0], v1 = acc[im][jn][1];
            float v2 = acc[im][jn][2], v3 = acc[im][jn][3];
            if (ROUND) { v0 = tf32r(v0); v1 = tf32r(v1); v2 = tf32r(v2); v3 = tf32r(v3); }
            *(float2*)(C + (size_t)row * ldc + col)       = make_float2(v0, v1);
            *(float2*)(C + (size_t)(row + 8) * ldc + col) = make_float2(v2, v3);
        }
    }
}

// ---------------------------------------------------------------------------
// 0) Pre-round inputs to tf32 (so GEMM inner loops skip cvt entirely)
// ---------------------------------------------------------------------------
__global__ __launch_bounds__(256) void round_x_kernel(const float4* __restrict__ x) {
    const int n4 = BATCH * SEQ * DIM / 4;
    float4* dst = (float4*)d_xr;
    for (int i = blockIdx.x * 256 + threadIdx.x; i < n4; i += gridDim.x * 256) {
        float4 v = x[i];
        v.x = tf32r(v.x); v.y = tf32r(v.y); v.z = tf32r(v.z); v.w = tf32r(v.w);
        dst[i] = v;
    }
}

__global__ __launch_bounds__(256) void round_w_kernel(const float4* __restrict__ Wq,
                                                      const float4* __restrict__ Wk,
                                                      const float4* __restrict__ Wv) {
    const float4* src = (blockIdx.z == 0) ? Wq : (blockIdx.z == 1) ? Wk : Wv;
    float4* dst = (float4*)d_Wr[blockIdx.z];
    const int n4 = DIM * DIM / 4;
    for (int i = blockIdx.x * 256 + threadIdx.x; i < n4; i += gridDim.x * 256) {
        float4 v = src[i];
        v.x = tf32r(v.x); v.y = tf32r(v.y); v.z = tf32r(v.z); v.w = tf32r(v.w);
        dst[i] = v;
    }
}

// ---------------------------------------------------------------------------
// 1) QKV projection: xr[8192,1024] @ Wr[1024,1024]^T  (NT, z selects weight)
//    Epilogue rounds Q/K/V to tf32 (they are mma operands downstream).
// ---------------------------------------------------------------------------
__global__ __launch_bounds__(256, 2) void qkv_kernel() {
    __shared__ float sA[2][128 * SA_STRIDE];
    __shared__ float sB[2][128 * SA_STRIDE];

    float* out = (blockIdx.z == 0) ? d_Q : (blockIdx.z == 1) ? d_K : d_V;
    const float* W = d_Wr[blockIdx.z];

    const int m0 = blockIdx.y * 128, n0 = blockIdx.x * 128;
    const int t = threadIdx.x;
    const int wid = t >> 5, lane = t & 31, g = lane >> 2, c = lane & 3;
    const int m_off = (wid >> 2) * 64, n_off = (wid & 3) * 32;
    const int aOff = (m_off + g) * SA_STRIDE + c;
    const int bOff = (n_off + g) * SA_STRIDE + c;

    const float* gA = d_xr + (size_t)m0 * DIM;
    const float* gB = W + (size_t)n0 * DIM;

    float acc[4][4][4] = {};
    const int nIter = DIM / 16;

    load_tile_kmajor(sA[0], gA, DIM, t);
    load_tile_kmajor(sB[0], gB, DIM, t);
    cp_commit();

    for (int it = 0; it < nIter; ++it) {
        if (it + 1 < nIter) {
            const int nb = (it + 1) & 1;
            load_tile_kmajor(sA[nb], gA + (it + 1) * 16, DIM, t);
            load_tile_kmajor(sB[nb], gB + (it + 1) * 16, DIM, t);
            cp_commit();
            cp_wait1();
        } else {
            cp_wait0();
        }
        __syncthreads();
        const int s = it & 1;
        mma_step_NT(sA[s] + aOff, sB[s] + bOff, acc);
        __syncthreads();
    }
    store_acc<true>(out, DIM, m0, n0, m_off, n_off, g, c, acc);
}

// ---------------------------------------------------------------------------
// 2) Scores: S[b] = Q[b] @ K[b]^T  (NT, lower-triangular tiles only)
//    Output left fp32 (softmax wants precision; it rounds its own output).
// ---------------------------------------------------------------------------
__global__ __launch_bounds__(256, 2) void scores_kernel() {
    if (blockIdx.x > blockIdx.y) return;  // fully-masked tile: never read later

    __shared__ float sA[2][128 * SA_STRIDE];
    __shared__ float sB[2][128 * SA_STRIDE];

    const int b = blockIdx.z;
    const int m0 = blockIdx.y * 128, n0 = blockIdx.x * 128;
    const int t = threadIdx.x;
    const int wid = t >> 5, lane = t & 31, g = lane >> 2, c = lane & 3;
    const int m_off = (wid >> 2) * 64, n_off = (wid & 3) * 32;
    const int aOff = (m_off + g) * SA_STRIDE + c;
    const int bOff = (n_off + g) * SA_STRIDE + c;

    const float* gA = d_Q + (size_t)b * SEQ * DIM + (size_t)m0 * DIM;
    const float* gB = d_K + (size_t)b * SEQ * DIM + (size_t)n0 * DIM;
    float* C = d_S + (size_t)b * SEQ * SEQ;

    float acc[4][4][4] = {};
    const int nIter = DIM / 16;

    load_tile_kmajor(sA[0], gA, DIM, t);
    load_tile_kmajor(sB[0], gB, DIM, t);
    cp_commit();

    for (int it = 0; it < nIter; ++it) {
        if (it + 1 < nIter) {
            const int nb = (it + 1) & 1;
            load_tile_kmajor(sA[nb], gA + (it + 1) * 16, DIM, t);
            load_tile_kmajor(sB[nb], gB + (it + 1) * 16, DIM, t);
            cp_commit();
            cp_wait1();
        } else {
            cp_wait0();
        }
        __syncthreads();
        const int s = it & 1;
        mma_step_NT(sA[s] + aOff, sB[s] + bOff, acc);
        __syncthreads();
    }
    store_acc<false>(C, SEQ, m0, n0, m_off, n_off, g, c, acc);
}

// ---------------------------------------------------------------------------
// 3) Causal softmax; probabilities written tf32-rounded (they feed PV's mma).
// ---------------------------------------------------------------------------
__global__ __launch_bounds__(256) void softmax_kernel() {
    const int i = blockIdx.x;
    const int b = blockIdx.y;
    float* row = d_S + ((size_t)b * SEQ + i) * SEQ;
    const float scale = 0.03125f;   // 1/sqrt(1024)
    const int len = i + 1;
    const int t = threadIdx.x;

    __shared__ float red[256];

    float m = -CUDART_INF_F;
    for (int j = t; j < len; j += 256) m = fmaxf(m, row[j]);
    red[t] = m; __syncthreads();
    for (int s = 128; s > 0; s >>= 1) {
        if (t < s) red[t] = fmaxf(red[t], red[t + s]);
        __syncthreads();
    }
    m = red[0] * scale;
    __syncthreads();

    float sum = 0.f;
    for (int j = t; j < len; j += 256) {
        float e = __expf(row[j] * scale - m);
        row[j] = e;
        sum += e;
    }
    red[t] = sum; __syncthreads();
    for (int s = 128; s > 0; s >>= 1) {
        if (t < s) red[t] += red[t + s];
        __syncthreads();
    }
    const float inv = 1.f / red[0];

    for (int j = t; j < len; j += 256) row[j] = tf32r(row[j] * inv);
    for (int j = len + t; j < SEQ; j += 256) row[j] = 0.f;   // zero pad for PV reads
}

// ---------------------------------------------------------------------------
// 4) O = P @ V  (NN, k-loop truncated at the query tile's diagonal)
// ---------------------------------------------------------------------------
__global__ __launch_bounds__(256, 2) void pv_kernel(float* __restrict__ out) {
    __shared__ float sA[2][128 * SA_STRIDE];
    __shared__ float sB[2][16 * SBNN_STRIDE];

    const int b = blockIdx.z;
    const int m0 = blockIdx.y * 128, n0 = blockIdx.x * 128;
    const int t = threadIdx.x;
    const int wid = t >> 5, lane = t & 31, g = lane >> 2, c = lane & 3;
    const int m_off = (wid >> 2) * 64, n_off = (wid & 3) * 32;
    const int aOff = (m_off + g) * SA_STRIDE + c;
    const int bOff = c * SBNN_STRIDE + n_off + g;

    const float* gA = d_S + (size_t)b * SEQ * SEQ + (size_t)m0 * SEQ;
    const float* gB = d_V + (size_t)b * SEQ * DIM + n0;
    float* C = out + (size_t)b * SEQ * DIM;

    float acc[4][4][4] = {};
    const int nIter = (m0 + 128) / 16;   // P[m, k>m] == 0, tile-aligned

    load_tile_kmajor(sA[0], gA, SEQ, t);
    load_tile_nmajor(sB[0], gB, DIM, t);
    cp_commit();

    for (int it = 0; it < nIter; ++it) {
        if (it + 1 < nIter) {
            const int nb = (it + 1) & 1;
            load_tile_kmajor(sA[nb], gA + (it + 1) * 16, SEQ, t);
            load_tile_nmajor(sB[nb], gB + (size_t)(it + 1) * 16 * DIM, DIM, t);
            cp_commit();
            cp_wait1();
        } else {
            cp_wait0();
        }
        __syncthreads();
        const int s = it & 1;
        mma_step_NN(sA[s] + aOff, sB[s] + bOff, acc);
        __syncthreads();
    }
    store_acc<false>(C, DIM, m0, n0, m_off, n_off, g, c, acc);
}

extern "C" void kernel_launch(void* const* d_in, const int* in_sizes, int n_in,
                              void* d_out, int out_size) {
    const float* x  = (const float*)d_in[0];
    const float* Wq = (const float*)d_in[1];
    const float* Wk = (const float*)d_in[2];
    const float* Wv = (const float*)d_in[3];
    float* out = (float*)d_out;

    // 0) tf32 pre-rounding of x and W
    round_x_kernel<<<512, 256>>>((const float4*)x);
    round_w_kernel<<<dim3(64, 1, 3), 256>>>((const float4*)Wq, (const float4*)Wk,
                                            (const float4*)Wv);

    // 1) Q,K,V projections: M=8192, N=1024, z selects weight (outputs rounded)
    qkv_kernel<<<dim3(DIM / 128, (BATCH * SEQ) / 128, 3), 256>>>();

    // 2) Scores = Q K^T per batch (lower-triangular tiles only)
    scores_kernel<<<dim3(SEQ / 128, SEQ / 128, BATCH), 256>>>();

    // 3) Causal softmax (probabilities tf32-rounded)
    softmax_kernel<<<dim3(SEQ, BATCH), 256>>>();

    // 4) O = P V per batch (k-loop truncated at diagonal)
    pv_kernel<<<dim3(DIM / 128, SEQ / 128, BATCH), 256>>>(out);
}

// round 7
// speedup vs baseline: 1.0121x; 1.0121x over previous
#include <cuda_runtime.h>
#include <math_constants.h>

#define BATCH 4
#define SEQ   2048
#define DIM   1024

// Scratch (static device arrays: allocation-guard-safe)
__device__ float d_Q[BATCH * SEQ * DIM];
__device__ float d_K[BATCH * SEQ * DIM];
__device__ float d_V[BATCH * SEQ * DIM];
__device__ float d_S[(size_t)BATCH * SEQ * SEQ];   // scores -> unnorm. probs in place
__device__ float d_inv[BATCH * SEQ];               // 1/rowsum for deferred normalize
__device__ float d_xr[BATCH * SEQ * DIM];          // tf32-rounded x
__device__ float d_Wr[3][DIM * DIM];               // tf32-rounded Wq/Wk/Wv

// ---------------------------------------------------------------------------
// TF32 tensor-core GEMM: block tile 128x128, BK=32, 3-stage cp.async pipeline,
// ONE __syncthreads per iteration. 256 threads = 8 warps (2x4), warp 64x32.
// Operands pre-rounded to tf32 in gmem (no cvt in hot loop).
// ---------------------------------------------------------------------------

#define BK 32
#define SA_ST 36     // 32 + 4 pad: (36*g + c) % 32 == 4g + c -> conflict-free frags
#define SB_ST 136    // 128 + 8 pad for [k][n] V tile

#define SMEM_NT (3 * 128 * SA_ST * 4 * 2)                       // 110592 B
#define SMEM_PV (3 * 128 * SA_ST * 4 + 3 * BK * SB_ST * 4)      // 107520 B

__device__ __forceinline__ unsigned f2tf(float x) {
    unsigned u;
    asm("cvt.rna.tf32.f32 %0, %1;" : "=r"(u) : "f"(x));
    return u;
}
__device__ __forceinline__ float tf32r(float x) { return __uint_as_float(f2tf(x)); }

__device__ __forceinline__ void mma_tf32(float* d, const unsigned* a, const unsigned* b) {
    asm volatile(
        "mma.sync.aligned.m16n8k8.row.col.f32.tf32.tf32.f32 "
        "{%0,%1,%2,%3}, {%4,%5,%6,%7}, {%8,%9}, {%0,%1,%2,%3};\n"
        : "+f"(d[0]), "+f"(d[1]), "+f"(d[2]), "+f"(d[3])
        : "r"(a[0]), "r"(a[1]), "r"(a[2]), "r"(a[3]), "r"(b[0]), "r"(b[1]));
}

__device__ __forceinline__ void cp16(void* smem, const void* gmem) {
    unsigned s = (unsigned)__cvta_generic_to_shared(smem);
    asm volatile("cp.async.cg.shared.global [%0], [%1], 16;\n" :: "r"(s), "l"(gmem));
}
__device__ __forceinline__ void cp_commit() { asm volatile("cp.async.commit_group;\n"); }
__device__ __forceinline__ void cp_wait1()  { asm volatile("cp.async.wait_group 1;\n"); }

// 128x32 K-contiguous tile into smem [128][SA_ST] (4 cp16/thread).
__device__ __forceinline__ void load_km(float* s, const float* g, int ld, int t) {
    const int row = t >> 2;            // 0..63
    const int c4  = (t & 3) << 2;      // 0,4,8,12
#pragma unroll
    for (int cb = 0; cb < 32; cb += 16) {
        cp16(&s[row * SA_ST + cb + c4],        g + (size_t)row * ld + cb + c4);
        cp16(&s[(row + 64) * SA_ST + cb + c4], g + (size_t)(row + 64) * ld + cb + c4);
    }
}

// 32x128 [k][n] tile (V) into smem [32][SB_ST] (4 cp16/thread).
__device__ __forceinline__ void load_nm(float* s, const float* g, int ld, int t) {
    const int kr = t >> 5;             // 0..7
    const int c4 = (t & 31) << 2;      // 0..124
#pragma unroll
    for (int rb = 0; rb < 32; rb += 16) {
        cp16(&s[(rb + kr) * SB_ST + c4],     g + (size_t)(rb + kr) * ld + c4);
        cp16(&s[(rb + kr + 8) * SB_ST + c4], g + (size_t)(rb + kr + 8) * ld + c4);
    }
}

// BK=32 compute step, NT. aBase = sA + (m_off+g)*SA_ST + c, bBase likewise.
__device__ __forceinline__ void mma_step_NT(const float* aBase, const float* bBase,
                                            float acc[4][4][4]) {
#pragma unroll
    for (int kb = 0; kb < BK; kb += 8) {
        unsigned a[4][4], b[4][2];
#pragma unroll
        for (int im = 0; im < 4; ++im) {
            const int r = im * 16 * SA_ST;
            a[im][0] = __float_as_uint(aBase[r + kb]);
            a[im][1] = __float_as_uint(aBase[r + 8 * SA_ST + kb]);
            a[im][2] = __float_as_uint(aBase[r + kb + 4]);
            a[im][3] = __float_as_uint(aBase[r + 8 * SA_ST + kb + 4]);
        }
#pragma unroll
        for (int jn = 0; jn < 4; ++jn) {
            const int nn = jn * 8 * SA_ST;
            b[jn][0] = __float_as_uint(bBase[nn + kb]);
            b[jn][1] = __float_as_uint(bBase[nn + kb + 4]);
        }
#pragma unroll
        for (int im = 0; im < 4; ++im)
#pragma unroll
            for (int jn = 0; jn < 4; ++jn)
                mma_tf32(acc[im][jn], a[im], b[jn]);
    }
}

// BK=32 compute step, NN. bBase = sB + c*SB_ST + n_off + g.
__device__ __forceinline__ void mma_step_NN(const float* aBase, const float* bBase,
                                            float acc[4][4][4]) {
#pragma unroll
    for (int kb = 0; kb < BK; kb += 8) {
        unsigned a[4][4], b[4][2];
#pragma unroll
        for (int im = 0; im < 4; ++im) {
            const int r = im * 16 * SA_ST;
            a[im][0] = __float_as_uint(aBase[r + kb]);
            a[im][1] = __float_as_uint(aBase[r + 8 * SA_ST + kb]);
            a[im][2] = __float_as_uint(aBase[r + kb + 4]);
            a[im][3] = __float_as_uint(aBase[r + 8 * SA_ST + kb + 4]);
        }
#pragma unroll
        for (int jn = 0; jn < 4; ++jn) {
            const int nn = jn * 8;
            b[jn][0] = __float_as_uint(bBase[kb * SB_ST + nn]);
            b[jn][1] = __float_as_uint(bBase[(kb + 4) * SB_ST + nn]);
        }
#pragma unroll
        for (int im = 0; im < 4; ++im)
#pragma unroll
            for (int jn = 0; jn < 4; ++jn)
                mma_tf32(acc[im][jn], a[im], b[jn]);
    }
}

template <bool ROUND>
__device__ __forceinline__ void store_acc(float* C, int ldc, int m0, int n0,
                                          int m_off, int n_off, int g, int c,
                                          float acc[4][4][4]) {
#pragma unroll
    for (int im = 0; im < 4; ++im) {
#pragma unroll
        for (int jn = 0; jn < 4; ++jn) {
            const int row = m0 + m_off + im * 16 + g;
            const int col = n0 + n_off + jn * 8 + 2 * c;
            float v0 = acc[im][jn][0], v1 = acc[im][jn][1];
            float v2 = acc[im][jn][2], v3 = acc[im][jn][3];
            if (ROUND) { v0 = tf32r(v0); v1 = tf32r(v1); v2 = tf32r(v2); v3 = tf32r(v3); }
            *(float2*)(C + (size_t)row * ldc + col)       = make_float2(v0, v1);
            *(float2*)(C + (size_t)(row + 8) * ldc + col) = make_float2(v2, v3);
        }
    }
}

// ---------------------------------------------------------------------------
// 0) Pre-round inputs to tf32
// ---------------------------------------------------------------------------
__global__ __launch_bounds__(256) void round_x_kernel(const float4* __restrict__ x) {
    const int n4 = BATCH * SEQ * DIM / 4;
    float4* dst = (float4*)d_xr;
    for (int i = blockIdx.x * 256 + threadIdx.x; i < n4; i += gridDim.x * 256) {
        float4 v = x[i];
        v.x = tf32r(v.x); v.y = tf32r(v.y); v.z = tf32r(v.z); v.w = tf32r(v.w);
        dst[i] = v;
    }
}

__global__ __launch_bounds__(256) void round_w_kernel(const float4* __restrict__ Wq,
                                                      const float4* __restrict__ Wk,
                                                      const float4* __restrict__ Wv) {
    const float4* src = (blockIdx.z == 0) ? Wq : (blockIdx.z == 1) ? Wk : Wv;
    float4* dst = (float4*)d_Wr[blockIdx.z];
    const int n4 = DIM * DIM / 4;
    for (int i = blockIdx.x * 256 + threadIdx.x; i < n4; i += gridDim.x * 256) {
        float4 v = src[i];
        v.x = tf32r(v.x); v.y = tf32r(v.y); v.z = tf32r(v.z); v.w = tf32r(v.w);
        dst[i] = v;
    }
}

// ---------------------------------------------------------------------------
// 1) QKV projection: xr @ Wr^T  (NT; outputs tf32-rounded)
// ---------------------------------------------------------------------------
__global__ __launch_bounds__(256, 2) void qkv_kernel() {
    extern __shared__ float smem[];
    float* sA = smem;                       // 3 stages of 128*SA_ST
    float* sB = smem + 3 * 128 * SA_ST;

    float* out = (blockIdx.z == 0) ? d_Q : (blockIdx.z == 1) ? d_K : d_V;
    const float* W = d_Wr[blockIdx.z];

    const int m0 = blockIdx.y * 128, n0 = blockIdx.x * 128;
    const int t = threadIdx.x;
    const int wid = t >> 5, lane = t & 31, g = lane >> 2, c = lane & 3;
    const int m_off = (wid >> 2) * 64, n_off = (wid & 3) * 32;
    const int aOff = (m_off + g) * SA_ST + c;
    const int bOff = (n_off + g) * SA_ST + c;

    const float* gA = d_xr + (size_t)m0 * DIM;
    const float* gB = W + (size_t)n0 * DIM;

    float acc[4][4][4] = {};
    const int nIter = DIM / BK;            // 32

    load_km(sA, gA, DIM, t); load_km(sB, gB, DIM, t); cp_commit();
    load_km(sA + 128 * SA_ST, gA + BK, DIM, t);
    load_km(sB + 128 * SA_ST, gB + BK, DIM, t); cp_commit();

    for (int it = 0; it < nIter; ++it) {
        cp_wait1();
        __syncthreads();
        const int pf = it + 2;
        if (pf < nIter) {
            const int ps = (pf % 3) * 128 * SA_ST;
            load_km(sA + ps, gA + pf * BK, DIM, t);
            load_km(sB + ps, gB + pf * BK, DIM, t);
        }
        cp_commit();
        const int s = (it % 3) * 128 * SA_ST;
        mma_step_NT(sA + s + aOff, sB + s + bOff, acc);
    }
    store_acc<true>(out, DIM, m0, n0, m_off, n_off, g, c, acc);
}

// ---------------------------------------------------------------------------
// 2) Scores: S[b] = Q[b] @ K[b]^T  (NT, lower-triangular tiles only)
// ---------------------------------------------------------------------------
__global__ __launch_bounds__(256, 2) void scores_kernel() {
    if (blockIdx.x > blockIdx.y) return;

    extern __shared__ float smem[];
    float* sA = smem;
    float* sB = smem + 3 * 128 * SA_ST;

    const int b = blockIdx.z;
    const int m0 = blockIdx.y * 128, n0 = blockIdx.x * 128;
    const int t = threadIdx.x;
    const int wid = t >> 5, lane = t & 31, g = lane >> 2, c = lane & 3;
    const int m_off = (wid >> 2) * 64, n_off = (wid & 3) * 32;
    const int aOff = (m_off + g) * SA_ST + c;
    const int bOff = (n_off + g) * SA_ST + c;

    const float* gA = d_Q + (size_t)b * SEQ * DIM + (size_t)m0 * DIM;
    const float* gB = d_K + (size_t)b * SEQ * DIM + (size_t)n0 * DIM;
    float* C = d_S + (size_t)b * SEQ * SEQ;

    float acc[4][4][4] = {};
    const int nIter = DIM / BK;

    load_km(sA, gA, DIM, t); load_km(sB, gB, DIM, t); cp_commit();
    load_km(sA + 128 * SA_ST, gA + BK, DIM, t);
    load_km(sB + 128 * SA_ST, gB + BK, DIM, t); cp_commit();

    for (int it = 0; it < nIter; ++it) {
        cp_wait1();
        __syncthreads();
        const int pf = it + 2;
        if (pf < nIter) {
            const int ps = (pf % 3) * 128 * SA_ST;
            load_km(sA + ps, gA + pf * BK, DIM, t);
            load_km(sB + ps, gB + pf * BK, DIM, t);
        }
        cp_commit();
        const int s = (it % 3) * 128 * SA_ST;
        mma_step_NT(sA + s + aOff, sB + s + bOff, acc);
    }
    store_acc<false>(C, SEQ, m0, n0, m_off, n_off, g, c, acc);
}

// ---------------------------------------------------------------------------
// 3) Causal softmax: write tf32(unnormalized exp) + 1/rowsum; zero only to
//    the 128-aligned tile end (PV never reads past it). Warp-shuffle reductions.
// ---------------------------------------------------------------------------
__global__ __launch_bounds__(256) void softmax_kernel() {
    const int i = blockIdx.x;
    const int b = blockIdx.y;
    float* row = d_S + ((size_t)b * SEQ + i) * SEQ;
    const float scale = 0.03125f;   // 1/sqrt(1024)
    const int len = i + 1;
    const int tileEnd = ((i >> 7) + 1) << 7;
    const int t = threadIdx.x;
    const int lane = t & 31, w = t >> 5;

    __shared__ float red[8];

    float m = -CUDART_INF_F;
    for (int j = t; j < len; j += 256) m = fmaxf(m, row[j]);
#pragma unroll
    for (int o = 16; o > 0; o >>= 1) m = fmaxf(m, __shfl_xor_sync(0xffffffffu, m, o));
    if (lane == 0) red[w] = m;
    __syncthreads();
    m = red[lane & 7];
#pragma unroll
    for (int o = 4; o > 0; o >>= 1) m = fmaxf(m, __shfl_xor_sync(0xffffffffu, m, o));
    m *= scale;
    __syncthreads();

    float sum = 0.f;
    for (int j = t; j < len; j += 256) {
        float e = __expf(row[j] * scale - m);
        row[j] = tf32r(e);
        sum += e;
    }
#pragma unroll
    for (int o = 16; o > 0; o >>= 1) sum += __shfl_xor_sync(0xffffffffu, sum, o);
    if (lane == 0) red[w] = sum;
    __syncthreads();
    sum = red[lane & 7];
#pragma unroll
    for (int o = 4; o > 0; o >>= 1) sum += __shfl_xor_sync(0xffffffffu, sum, o);
    if (t == 0) d_inv[b * SEQ + i] = 1.f / sum;

    for (int j = len + t; j < tileEnd; j += 256) row[j] = 0.f;
}

// ---------------------------------------------------------------------------
// 4) O = P @ V  (NN, k truncated at diagonal; epilogue scales by 1/rowsum)
// ---------------------------------------------------------------------------
__global__ __launch_bounds__(256, 2) void pv_kernel(float* __restrict__ out) {
    extern __shared__ float smem[];
    float* sA = smem;
    float* sB = smem + 3 * 128 * SA_ST;    // 3 stages of BK*SB_ST

    const int b = blockIdx.z;
    const int m0 = blockIdx.y * 128, n0 = blockIdx.x * 128;
    const int t = threadIdx.x;
    const int wid = t >> 5, lane = t & 31, g = lane >> 2, c = lane & 3;
    const int m_off = (wid >> 2) * 64, n_off = (wid & 3) * 32;
    const int aOff = (m_off + g) * SA_ST + c;
    const int bOff = c * SB_ST + n_off + g;

    const float* gA = d_S + (size_t)b * SEQ * SEQ + (size_t)m0 * SEQ;
    const float* gB = d_V + (size_t)b * SEQ * DIM + n0;
    float* C = out + (size_t)b * SEQ * DIM;

    float acc[4][4][4] = {};
    const int nIter = (m0 + 128) / BK;     // >= 4

    load_km(sA, gA, SEQ, t); load_nm(sB, gB, DIM, t); cp_commit();
    load_km(sA + 128 * SA_ST, gA + BK, SEQ, t);
    load_nm(sB + BK * SB_ST, gB + (size_t)BK * DIM, DIM, t); cp_commit();

    for (int it = 0; it < nIter; ++it) {
        cp_wait1();
        __syncthreads();
        const int pf = it + 2;
        if (pf < nIter) {
            load_km(sA + (pf % 3) * 128 * SA_ST, gA + pf * BK, SEQ, t);
            load_nm(sB + (pf % 3) * BK * SB_ST, gB + (size_t)pf * BK * DIM, DIM, t);
        }
        cp_commit();
        mma_step_NN(sA + (it % 3) * 128 * SA_ST + aOff,
                    sB + (it % 3) * BK * SB_ST + bOff, acc);
    }

    const float* inv = d_inv + b * SEQ;
#pragma unroll
    for (int im = 0; im < 4; ++im) {
        const int row = m0 + m_off + im * 16 + g;
        const float i0 = inv[row], i1 = inv[row + 8];
#pragma unroll
        for (int jn = 0; jn < 4; ++jn) {
            const int col = n0 + n_off + jn * 8 + 2 * c;
            *(float2*)(C + (size_t)row * DIM + col) =
                make_float2(acc[im][jn][0] * i0, acc[im][jn][1] * i0);
            *(float2*)(C + (size_t)(row + 8) * DIM + col) =
                make_float2(acc[im][jn][2] * i1, acc[im][jn][3] * i1);
        }
    }
}

extern "C" void kernel_launch(void* const* d_in, const int* in_sizes, int n_in,
                              void* d_out, int out_size) {
    const float* x  = (const float*)d_in[0];
    const float* Wq = (const float*)d_in[1];
    const float* Wk = (const float*)d_in[2];
    const float* Wv = (const float*)d_in[3];
    float* out = (float*)d_out;

    cudaFuncSetAttribute(qkv_kernel,    cudaFuncAttributeMaxDynamicSharedMemorySize, SMEM_NT);
    cudaFuncSetAttribute(scores_kernel, cudaFuncAttributeMaxDynamicSharedMemorySize, SMEM_NT);
    cudaFuncSetAttribute(pv_kernel,     cudaFuncAttributeMaxDynamicSharedMemorySize, SMEM_PV);

    round_x_kernel<<<512, 256>>>((const float4*)x);
    round_w_kernel<<<dim3(64, 1, 3), 256>>>((const float4*)Wq, (const float4*)Wk,
                                            (const float4*)Wv);

    qkv_kernel<<<dim3(DIM / 128, (BATCH * SEQ) / 128, 3), 256, SMEM_NT>>>();
    scores_kernel<<<dim3(SEQ / 128, SEQ / 128, BATCH), 256, SMEM_NT>>>();
    softmax_kernel<<<dim3(SEQ, BATCH), 256>>>();
    pv_kernel<<<dim3(DIM / 128, SEQ / 128, BATCH), 256, SMEM_PV>>>(out);
}